// round 3
// baseline (speedup 1.0000x reference)
#include <cuda_runtime.h>
#include <math_constants.h>

#define D 128

// scratch (no allocations allowed)
static __device__ unsigned long long g_best[20480];  // packed (monotonic dist << 32) | idx
static __device__ float g_y2[16384];

// ---------------- y2[j] = ||rain_j||^2 ----------------
__global__ void y2_kernel(const float* __restrict__ B, int M) {
    int warp = (blockIdx.x * blockDim.x + threadIdx.x) >> 5;
    int lane = threadIdx.x & 31;
    if (warp >= M) return;
    const float4* row = (const float4*)(B + (size_t)warp * D);
    float4 v = row[lane];
    float s = v.x * v.x + v.y * v.y + v.z * v.z + v.w * v.w;
    #pragma unroll
    for (int o = 16; o > 0; o >>= 1) s += __shfl_xor_sync(0xffffffffu, s, o);
    if (lane == 0) g_y2[warp] = s;
}

__global__ void init_best(int N) {
    int i = blockIdx.x * blockDim.x + threadIdx.x;
    if (i < N) g_best[i] = 0xFFFFFFFFFFFFFFFFull;
}

// ---------------- argmin GEMM ----------------
// block: 256 threads, computes BM x BN dot-product tile per M-tile.
// tx in [0,16): column group (TN=8 cols), ty in [0,16): row group (TM=4 rows)
constexpr int BM = 64;
constexpr int BN = 128;
constexpr int BK = 16;
constexpr int TM = 4;
constexpr int TN = 8;
constexpr int MSPLIT = 4;

__global__ __launch_bounds__(256, 3)
void argmin_kernel(const float* __restrict__ A, const float* __restrict__ Bm,
                   int N, int M) {
    __shared__ float As[D][BM];                // 32 KB, A stripe transposed, resident
    __shared__ union {
        struct { float Bs[BK][BN]; float y2s[BN]; } t;   // 8.5 KB
        struct { float rv[BM][16]; int ri[BM][16]; } r;  // 8 KB
    } u;

    int tid = threadIdx.x;
    int tx = tid & 15, ty = tid >> 4;
    int row0 = blockIdx.x * BM;
    int r0 = ty * TM;
    int c0 = tx * TN;

    // load A stripe [BM][D] -> As[k][r] (transposed). 2048 float4s, 8 per thread.
    #pragma unroll
    for (int it = 0; it < 8; ++it) {
        int lin = tid + it * 256;      // float4 index
        int r = lin >> 5;              // row within stripe
        int kq = lin & 31;             // which float4 along D
        int gr = min(row0 + r, N - 1);
        float4 v = ((const float4*)(A + (size_t)gr * D))[kq];
        As[kq * 4 + 0][r] = v.x;
        As[kq * 4 + 1][r] = v.y;
        As[kq * 4 + 2][r] = v.z;
        As[kq * 4 + 3][r] = v.w;
    }

    int chunk = (M + MSPLIT - 1) / MSPLIT;
    int j0 = blockIdx.y * chunk;
    int j_end = min(j0 + chunk, M);

    float best[TM];
    int besti[TM];
    #pragma unroll
    for (int i = 0; i < TM; i++) { best[i] = CUDART_INF_F; besti[i] = 0x7FFFFFFF; }

    for (int jt = j0; jt < j_end; jt += BN) {
        __syncthreads();   // protect y2s/Bs vs previous tile's epilogue readers
        if (tid < BN) {
            int j = jt + tid;
            u.t.y2s[tid] = (j < j_end) ? g_y2[j] : CUDART_INF_F;
        }

        float acc[TM][TN];
        #pragma unroll
        for (int i = 0; i < TM; i++)
            #pragma unroll
            for (int jj = 0; jj < TN; jj++) acc[i][jj] = 0.f;

        #pragma unroll 1
        for (int kk = 0; kk < D; kk += BK) {
            __syncthreads();
            // load B chunk [BN][BK] -> Bs[k][c]. 512 float4s, 2 per thread.
            #pragma unroll
            for (int l = 0; l < 2; l++) {
                int lin = tid * 2 + l;
                int c = lin >> 2;
                int kq = lin & 3;
                int gj = min(jt + c, M - 1);
                float4 v = ((const float4*)(Bm + (size_t)gj * D + kk))[kq];
                u.t.Bs[kq * 4 + 0][c] = v.x;
                u.t.Bs[kq * 4 + 1][c] = v.y;
                u.t.Bs[kq * 4 + 2][c] = v.z;
                u.t.Bs[kq * 4 + 3][c] = v.w;
            }
            __syncthreads();
            #pragma unroll
            for (int k = 0; k < BK; k++) {
                float4 av = *(const float4*)&As[kk + k][r0];
                float a[TM] = {av.x, av.y, av.z, av.w};
                float4 b0 = *(const float4*)&u.t.Bs[k][c0];
                float4 b1 = *(const float4*)&u.t.Bs[k][c0 + 4];
                float b[TN] = {b0.x, b0.y, b0.z, b0.w, b1.x, b1.y, b1.z, b1.w};
                #pragma unroll
                for (int i = 0; i < TM; i++)
                    #pragma unroll
                    for (int jj = 0; jj < TN; jj++)
                        acc[i][jj] += a[i] * b[jj];
            }
        }

        // epilogue: dist = y2[j] - 2*dot (x2 term constant per row -> same argmin)
        #pragma unroll
        for (int i = 0; i < TM; i++) {
            #pragma unroll
            for (int jj = 0; jj < TN; jj++) {
                float dist = u.t.y2s[c0 + jj] - 2.f * acc[i][jj];
                int j = jt + c0 + jj;
                if (dist < best[i] || (dist == best[i] && j < besti[i])) {
                    best[i] = dist; besti[i] = j;
                }
            }
        }
    }

    // cross-thread reduction per row, then one packed atomicMin per row
    __syncthreads();
    #pragma unroll
    for (int i = 0; i < TM; i++) {
        u.r.rv[r0 + i][tx] = best[i];
        u.r.ri[r0 + i][tx] = besti[i];
    }
    __syncthreads();
    if (tid < BM) {
        int r = tid;
        float bv = u.r.rv[r][0]; int bi = u.r.ri[r][0];
        #pragma unroll
        for (int t = 1; t < 16; t++) {
            float v = u.r.rv[r][t]; int ix = u.r.ri[r][t];
            if (v < bv || (v == bv && ix < bi)) { bv = v; bi = ix; }
        }
        int row = row0 + r;
        if (row < N) {
            unsigned int uu = __float_as_uint(bv);
            uu = (uu & 0x80000000u) ? ~uu : (uu | 0x80000000u);  // monotonic map
            unsigned long long key = ((unsigned long long)uu << 32) | (unsigned int)bi;
            atomicMin(&g_best[row], key);
        }
    }
}

// ---------------- MLP + gated fusion ----------------
// one block per query, 128 threads (one per hidden/output channel)
__global__ __launch_bounds__(128)
void mlp_kernel(const float* __restrict__ clear, const float* __restrict__ rain,
                const float* __restrict__ W1, const float* __restrict__ b1,
                const float* __restrict__ W2, const float* __restrict__ b2,
                float* __restrict__ out, int N) {
    __shared__ float cs[D], als[D];
    __shared__ float hred[4];
    int i = blockIdx.x;
    int d = threadIdx.x;
    int idx = (int)(g_best[i] & 0xFFFFFFFFull);
    cs[d]  = clear[(size_t)i * D + d];
    als[d] = rain[(size_t)idx * D + d];
    __syncthreads();

    const float* w1r = W1 + (size_t)d * (2 * D);
    float h = b1[d];
    #pragma unroll
    for (int k = 0; k < D; k += 4) {
        float4 w = *(const float4*)(w1r + k);
        h += w.x * cs[k] + w.y * cs[k + 1] + w.z * cs[k + 2] + w.w * cs[k + 3];
    }
    #pragma unroll
    for (int k = 0; k < D; k += 4) {
        float4 w = *(const float4*)(w1r + D + k);
        h += w.x * als[k] + w.y * als[k + 1] + w.z * als[k + 2] + w.w * als[k + 3];
    }
    h = fmaxf(h, 0.f);

    float p = h * W2[d];
    #pragma unroll
    for (int o = 16; o > 0; o >>= 1) p += __shfl_xor_sync(0xffffffffu, p, o);
    if ((d & 31) == 0) hred[d >> 5] = p;
    __syncthreads();
    float s = hred[0] + hred[1] + hred[2] + hred[3] + b2[0];
    float w = 1.f / (1.f + __expf(-s));
    out[(size_t)i * D + d] = w * cs[d] + (1.f - w) * als[d];
}

extern "C" void kernel_launch(void* const* d_in, const int* in_sizes, int n_in,
                              void* d_out, int out_size) {
    const float* clear = (const float*)d_in[0];
    const float* rain  = (const float*)d_in[1];
    const float* W1    = (const float*)d_in[2];
    const float* b1    = (const float*)d_in[3];
    const float* W2    = (const float*)d_in[4];
    const float* b2    = (const float*)d_in[5];
    float* out = (float*)d_out;
    int N = in_sizes[0] / D;
    int M = in_sizes[1] / D;

    y2_kernel<<<(M * 32 + 255) / 256, 256>>>(rain, M);
    init_best<<<(N + 255) / 256, 256>>>(N);
    dim3 grid((N + BM - 1) / BM, MSPLIT);
    argmin_kernel<<<grid, 256>>>(clear, rain, N, M);
    mlp_kernel<<<N, 128>>>(clear, rain, W1, b1, W2, b2, out, N);
}

// round 5
// speedup vs baseline: 4.3297x; 4.3297x over previous
#include <cuda_runtime.h>
#include <cuda_fp16.h>
#include <math_constants.h>
#include <cstdint>

#define D 128
constexpr int NPAD = 20096;   // 157 * 128
constexpr int MPAD = 16384;
constexpr int KEXT = 384;     // [a0|a1|a0] x [b0|b0|b1]
constexpr int NCHUNK = 24;    // KEXT / 16
constexpr int MSPLIT = 8;
constexpr int MQ = 16;

// ---------------- device scratch ----------------
static __device__ unsigned long long g_best[NPAD];
static __device__ float g_y2[MPAD];
static __device__ __half g_Ah[(size_t)NCHUNK * NPAD * 16];   // [chunk][row][16]
static __device__ __half g_Bh[(size_t)NCHUNK * MPAD * 16];   // [chunk][j][16]

// ---------------- helpers ----------------
__device__ __forceinline__ uint32_t cvta_shared(const void* p) {
    uint32_t a;
    asm("{ .reg .u64 t; cvta.to.shared.u64 t, %1; cvt.u32.u64 %0, t; }" : "=r"(a) : "l"(p));
    return a;
}
__device__ __forceinline__ void cp16(uint32_t dst, const void* src) {
    asm volatile("cp.async.cg.shared.global [%0], [%1], 16;" :: "r"(dst), "l"(src));
}
#define CP_COMMIT() asm volatile("cp.async.commit_group;" ::: "memory")
#define CP_WAIT(n)  asm volatile("cp.async.wait_group %0;" :: "n"(n) : "memory")
#define LDSM4(r0,r1,r2,r3,addr) \
    asm volatile("ldmatrix.sync.aligned.m8n8.x4.shared.b16 {%0,%1,%2,%3}, [%4];" \
                 : "=r"(r0),"=r"(r1),"=r"(r2),"=r"(r3) : "r"(addr))
#define MMA16816(d0,d1,d2,d3,a0,a1,a2,a3,b0,b1) \
    asm volatile("mma.sync.aligned.m16n8k16.row.col.f32.f16.f16.f32 " \
                 "{%0,%1,%2,%3}, {%4,%5,%6,%7}, {%8,%9}, {%0,%1,%2,%3};" \
                 : "+f"(d0),"+f"(d1),"+f"(d2),"+f"(d3) \
                 : "r"(a0),"r"(a1),"r"(a2),"r"(a3),"r"(b0),"r"(b1))

// ---------------- prep: fp16 2-way split into chunk-tiled ext layouts ----------------
__global__ void prepA(const float* __restrict__ src, int N) {
    int i = blockIdx.x * blockDim.x + threadIdx.x;
    if (i >= NCHUNK * NPAD * 16) return;
    int h = i & 15, row = (i >> 4) % NPAD, c = i / (NPAD * 16);
    int kk = c * 16 + h;
    int seg = kk >> 7; if (seg == 2) seg = 0;          // A: [a0|a1|a0]
    __half out = __float2half_rn(0.f);
    if (row < N) {
        float x = src[row * D + (kk & 127)];
        __half h0 = __float2half_rn(x);
        out = seg ? __float2half_rn(x - __half2float(h0)) : h0;
    }
    g_Ah[i] = out;
}
__global__ void prepB(const float* __restrict__ src, int M) {
    int i = blockIdx.x * blockDim.x + threadIdx.x;
    if (i >= NCHUNK * MPAD * 16) return;
    int h = i & 15, row = (i >> 4) % MPAD, c = i / (MPAD * 16);
    int kk = c * 16 + h;
    int seg = (kk >> 7) == 2 ? 1 : 0;                  // B: [b0|b0|b1]
    __half out = __float2half_rn(0.f);
    if (row < M) {
        float x = src[row * D + (kk & 127)];
        __half h0 = __float2half_rn(x);
        out = seg ? __float2half_rn(x - __half2float(h0)) : h0;
    }
    g_Bh[i] = out;
}
__global__ void y2_kernel(const float* __restrict__ B, int M) {
    int j = (blockIdx.x * blockDim.x + threadIdx.x) >> 5;
    int lane = threadIdx.x & 31;
    if (j >= MPAD) return;
    if (j >= M) { if (lane == 0) g_y2[j] = CUDART_INF_F; return; }
    float4 v = ((const float4*)(B + (size_t)j * D))[lane];
    float s = v.x * v.x + v.y * v.y + v.z * v.z + v.w * v.w;
    #pragma unroll
    for (int o = 16; o > 0; o >>= 1) s += __shfl_xor_sync(0xffffffffu, s, o);
    if (lane == 0) g_y2[j] = s;
}
__global__ void init_best(int N) {
    int i = blockIdx.x * blockDim.x + threadIdx.x;
    if (i < N) g_best[i] = 0xFFFFFFFFFFFFFFFFull;
}

// ---------------- argmin GEMM (mma.sync, A resident, B double-buffered) ----------------
// smem: As [24 chunks][128 rows][32B] = 96KB at 0; Bs 2 x 8KB at 98304. Total 114688.
constexpr int AS_BYTES = NCHUNK * 128 * 32;   // 98304
constexpr int SMEM_BYTES = AS_BYTES + 2 * 8192;

__global__ __launch_bounds__(256, 2)
void argmin_mma(int N, int M) {
    extern __shared__ char smem[];
    const uint32_t AS = cvta_shared(smem);
    const uint32_t BS = AS + AS_BYTES;

    int tid = threadIdx.x, lane = tid & 31, wid = tid >> 5;
    int warp_m = wid >> 2, warp_n = wid & 3;
    int row0 = blockIdx.x * 128;
    int chunkM = (M + MSPLIT - 1) / MSPLIT;
    int j0 = blockIdx.y * chunkM;
    int ntiles = (chunkM + 127) >> 7;

    // load resident A-ext stripe (6144 x 16B)
    #pragma unroll
    for (int it = 0; it < 24; ++it) {
        int i = it * 256 + tid;
        int c = i >> 8, rem = i & 255, r = rem >> 1, c2 = rem & 1;
        uint4 v = *((const uint4*)(g_Ah + ((size_t)(c * NPAD + row0 + r) << 4)) + c2);
        uint32_t dst = AS + c * 4096 + r * 32 + ((c2 ^ ((r >> 2) & 1)) << 4);
        asm volatile("st.shared.v4.b32 [%0], {%1,%2,%3,%4};"
                     :: "r"(dst), "r"(v.x), "r"(v.y), "r"(v.z), "r"(v.w));
    }
    __syncthreads();

    // ldmatrix base byte offsets (16B-group xor swizzle; +16 rows preserves (r>>2)&1)
    uint32_t sw16 = (uint32_t)(((lane >> 4) ^ ((lane >> 2) & 1)) << 4);
    uint32_t a_off = (uint32_t)((warp_m * 64 + (lane & 15)) * 32) + sw16;
    uint32_t b_off = (uint32_t)((warp_n * 32 + (lane & 15)) * 32) + sw16;

    float best[8]; int besti[8];
    #pragma unroll
    for (int s = 0; s < 8; ++s) { best[s] = CUDART_INF_F; besti[s] = 0x7FFFFFFF; }

    for (int t = 0; t < ntiles; ++t) {
        int jt = j0 + t * 128;
        float d[4][4][4];
        #pragma unroll
        for (int mf = 0; mf < 4; ++mf)
            #pragma unroll
            for (int nf = 0; nf < 4; ++nf)
                #pragma unroll
                for (int c = 0; c < 4; ++c) d[mf][nf][c] = 0.f;

        // prologue: stage 0
        #pragma unroll
        for (int it = 0; it < 2; ++it) {
            int i = it * 256 + tid;
            int cl = i >> 8, rem = i & 255, r = rem >> 1, c2 = rem & 1;
            const char* src = (const char*)(g_Bh + ((size_t)(cl * MPAD + jt + r) << 4)) + c2 * 16;
            cp16(BS + cl * 4096 + r * 32 + ((c2 ^ ((r >> 2) & 1)) << 4), src);
        }
        CP_COMMIT();

        #pragma unroll 1
        for (int s = 0; s < 12; ++s) {
            if (s + 1 < 12) {
                int buf1 = (s + 1) & 1;
                #pragma unroll
                for (int it = 0; it < 2; ++it) {
                    int i = it * 256 + tid;
                    int cl = i >> 8, rem = i & 255, r = rem >> 1, c2 = rem & 1;
                    int cc = (s + 1) * 2 + cl;
                    const char* src = (const char*)(g_Bh + ((size_t)(cc * MPAD + jt + r) << 4)) + c2 * 16;
                    cp16(BS + buf1 * 8192 + cl * 4096 + r * 32 + ((c2 ^ ((r >> 2) & 1)) << 4), src);
                }
                CP_COMMIT();
                CP_WAIT(1);
            } else {
                CP_WAIT(0);
            }
            __syncthreads();

            int buf = s & 1;
            #pragma unroll
            for (int kc = 0; kc < 2; ++kc) {
                int c = s * 2 + kc;
                uint32_t a[4][4];
                #pragma unroll
                for (int mf = 0; mf < 4; ++mf)
                    LDSM4(a[mf][0], a[mf][1], a[mf][2], a[mf][3],
                          AS + c * 4096 + a_off + mf * 512);
                uint32_t b[2][4];
                #pragma unroll
                for (int nfp = 0; nfp < 2; ++nfp)
                    LDSM4(b[nfp][0], b[nfp][1], b[nfp][2], b[nfp][3],
                          BS + buf * 8192 + kc * 4096 + b_off + nfp * 512);
                #pragma unroll
                for (int mf = 0; mf < 4; ++mf)
                    #pragma unroll
                    for (int nf = 0; nf < 4; ++nf) {
                        int nfp = nf >> 1, o = nf & 1;
                        MMA16816(d[mf][nf][0], d[mf][nf][1], d[mf][nf][2], d[mf][nf][3],
                                 a[mf][0], a[mf][1], a[mf][2], a[mf][3],
                                 b[nfp][o], b[nfp][2 + o]);
                    }
            }
            __syncthreads();
        }

        // epilogue: dist = y2[j] - 2*dot, thread-local argmin
        #pragma unroll
        for (int mf = 0; mf < 4; ++mf)
            #pragma unroll
            for (int nf = 0; nf < 4; ++nf)
                #pragma unroll
                for (int c = 0; c < 4; ++c) {
                    int slot = mf * 2 + (c >> 1);
                    int j = jt + warp_n * 32 + nf * 8 + ((lane & 3) << 1) + (c & 1);
                    float dist = __ldg(&g_y2[j]) - 2.f * d[mf][nf][c];
                    if (dist < best[slot] || (dist == best[slot] && j < besti[slot])) {
                        best[slot] = dist; besti[slot] = j;
                    }
                }
    }

    // reduce: lane-quad shfl, then across warp_n via smem (reuse As region)
    __syncthreads();
    unsigned long long* red = (unsigned long long*)smem;  // [128][4]
    #pragma unroll
    for (int slot = 0; slot < 8; ++slot) {
        uint32_t uu = __float_as_uint(best[slot]);
        uu = (uu & 0x80000000u) ? ~uu : (uu | 0x80000000u);
        unsigned long long key = ((unsigned long long)uu << 32) | (uint32_t)besti[slot];
        unsigned long long o1 = __shfl_xor_sync(0xffffffffu, key, 1); if (o1 < key) key = o1;
        unsigned long long o2 = __shfl_xor_sync(0xffffffffu, key, 2); if (o2 < key) key = o2;
        if ((lane & 3) == 0) {
            int rl = warp_m * 64 + (slot >> 1) * 16 + (lane >> 2) + (slot & 1) * 8;
            red[rl * 4 + warp_n] = key;
        }
    }
    __syncthreads();
    if (tid < 128) {
        unsigned long long k = red[tid * 4];
        #pragma unroll
        for (int w = 1; w < 4; ++w) {
            unsigned long long v = red[tid * 4 + w]; if (v < k) k = v;
        }
        int row = row0 + tid;
        if (row < N) atomicMin(&g_best[row], k);
    }
}

// ---------------- MLP + gated fusion (16 queries / block) ----------------
__global__ __launch_bounds__(128)
void mlp_kernel(const float* __restrict__ clear, const float* __restrict__ rain,
                const float* __restrict__ W1, const float* __restrict__ b1,
                const float* __restrict__ W2, const float* __restrict__ b2,
                float* __restrict__ out, int N) {
    __shared__ float cs[MQ][D], als[MQ][D];
    __shared__ float hred[MQ][4];
    int q0 = blockIdx.x * MQ;
    int d = threadIdx.x;
    #pragma unroll
    for (int q = 0; q < MQ; ++q) {
        int row = q0 + q; if (row >= N) row = N - 1;
        cs[q][d] = clear[(size_t)row * D + d];
        int idx = (int)(g_best[row] & 0xFFFFFFFFull);
        als[q][d] = rain[(size_t)idx * D + d];
    }
    __syncthreads();

    float h[MQ];
    float bb = b1[d];
    #pragma unroll
    for (int q = 0; q < MQ; ++q) h[q] = bb;

    const float4* w4 = (const float4*)(W1 + (size_t)d * (2 * D));
    #pragma unroll 4
    for (int k = 0; k < D / 4; ++k) {
        float4 w = w4[k];
        #pragma unroll
        for (int q = 0; q < MQ; ++q) {
            float4 c = *(const float4*)&cs[q][k * 4];
            h[q] += w.x * c.x + w.y * c.y + w.z * c.z + w.w * c.w;
        }
    }
    #pragma unroll 4
    for (int k = 0; k < D / 4; ++k) {
        float4 w = w4[D / 4 + k];
        #pragma unroll
        for (int q = 0; q < MQ; ++q) {
            float4 c = *(const float4*)&als[q][k * 4];
            h[q] += w.x * c.x + w.y * c.y + w.z * c.z + w.w * c.w;
        }
    }
    float w2d = W2[d];
    #pragma unroll
    for (int q = 0; q < MQ; ++q) {
        float p = fmaxf(h[q], 0.f) * w2d;
        #pragma unroll
        for (int o = 16; o > 0; o >>= 1) p += __shfl_xor_sync(0xffffffffu, p, o);
        if ((d & 31) == 0) hred[q][d >> 5] = p;
    }
    __syncthreads();
    float bias2 = b2[0];
    #pragma unroll
    for (int q = 0; q < MQ; ++q) {
        int row = q0 + q;
        if (row < N) {
            float s = hred[q][0] + hred[q][1] + hred[q][2] + hred[q][3] + bias2;
            float wq = 1.f / (1.f + __expf(-s));
            out[(size_t)row * D + d] = wq * cs[q][d] + (1.f - wq) * als[q][d];
        }
    }
}

extern "C" void kernel_launch(void* const* d_in, const int* in_sizes, int n_in,
                              void* d_out, int out_size) {
    const float* clear = (const float*)d_in[0];
    const float* rain  = (const float*)d_in[1];
    const float* W1    = (const float*)d_in[2];
    const float* b1    = (const float*)d_in[3];
    const float* W2    = (const float*)d_in[4];
    const float* b2    = (const float*)d_in[5];
    float* out = (float*)d_out;
    int N = in_sizes[0] / D;
    int M = in_sizes[1] / D;

    static int configured = 0;
    if (!configured) {
        cudaFuncSetAttribute(argmin_mma, cudaFuncAttributeMaxDynamicSharedMemorySize, SMEM_BYTES);
        configured = 1;
    }

    int nA = NCHUNK * NPAD * 16, nB = NCHUNK * MPAD * 16;
    prepA<<<(nA + 255) / 256, 256>>>(clear, N);
    prepB<<<(nB + 255) / 256, 256>>>(rain, M);
    y2_kernel<<<(MPAD * 32 + 255) / 256, 256>>>(rain, M);
    init_best<<<(N + 255) / 256, 256>>>(N);

    dim3 grid((N + 127) / 128, MSPLIT);
    argmin_mma<<<grid, 256, SMEM_BYTES>>>(N, M);

    mlp_kernel<<<(N + MQ - 1) / MQ, 128>>>(clear, rain, W1, b1, W2, b2, out, N);
}